// round 1
// baseline (speedup 1.0000x reference)
#include <cuda_runtime.h>

// Problem constants (fixed by the dataset: B=32, V=200000, F=400000).
#define BB 32
#define VV 200000
#define FF 400000
#define NV (BB * VV)   // 6,400,000 vertices total (divisible by 4)

// Static device scratch (allowed; no runtime allocation).
// g_vtx: vertices repacked to float4 (16B-aligned gathers, 1 L2 sector each)
// g_acc: per-vertex normal accumulator, float4 so we can use red.global.add.v4.f32
__device__ float4 g_vtx[NV];
__device__ float4 g_acc[NV];

// Vectorized global reduction: one RED instruction adds (x,y,z,0) to a float4.
__device__ __forceinline__ void red_add_v4(float4* addr, float x, float y, float z) {
    asm volatile("red.global.add.v4.f32 [%0], {%1, %2, %3, %4};"
                 :: "l"(addr), "f"(x), "f"(y), "f"(z), "f"(0.0f)
                 : "memory");
}

// Kernel 1: repack (B,V,3) f32 -> float4 (w unused) and zero the accumulator.
// Each thread handles 4 vertices = 12 input floats = 3 aligned float4 loads.
__global__ void repack_zero_kernel(const float* __restrict__ verts) {
    int t = blockIdx.x * blockDim.x + threadIdx.x;
    int gv = t * 4;
    if (gv >= NV) return;

    const float4* src = reinterpret_cast<const float4*>(verts + (size_t)gv * 3);
    float4 a = src[0];
    float4 b = src[1];
    float4 c = src[2];

    g_vtx[gv + 0] = make_float4(a.x, a.y, a.z, 0.0f);
    g_vtx[gv + 1] = make_float4(a.w, b.x, b.y, 0.0f);
    g_vtx[gv + 2] = make_float4(b.z, b.w, c.x, 0.0f);
    g_vtx[gv + 3] = make_float4(c.y, c.z, c.w, 0.0f);

    float4 z = make_float4(0.0f, 0.0f, 0.0f, 0.0f);
    g_acc[gv + 0] = z;
    g_acc[gv + 1] = z;
    g_acc[gv + 2] = z;
    g_acc[gv + 3] = z;
}

// Kernel 2: per (batch, face): gather 3 vertices, cross(e2, e1), scatter-add
// to the 3 face vertices with vectorized global reductions.
// grid.x covers faces, grid.y = batch (so same-batch CTAs launch contiguously
// and the per-batch 3.2MB accumulator slice stays L2-resident).
__global__ void accum_kernel(const int* __restrict__ faces) {
    int f = blockIdx.x * blockDim.x + threadIdx.x;
    if (f >= FF) return;
    int base = blockIdx.y * VV;

    int i0 = faces[3 * f + 0];
    int i1 = faces[3 * f + 1];
    int i2 = faces[3 * f + 2];

    float4 v0 = g_vtx[base + i0];
    float4 v1 = g_vtx[base + i1];
    float4 v2 = g_vtx[base + i2];

    // e1 = v0 - v1; e2 = v2 - v1; n = cross(e2, e1)
    float e1x = v0.x - v1.x, e1y = v0.y - v1.y, e1z = v0.z - v1.z;
    float e2x = v2.x - v1.x, e2y = v2.y - v1.y, e2z = v2.z - v1.z;

    float nx = e2y * e1z - e2z * e1y;
    float ny = e2z * e1x - e2x * e1z;
    float nz = e2x * e1y - e2y * e1x;

    red_add_v4(&g_acc[base + i0], nx, ny, nz);
    red_add_v4(&g_acc[base + i1], nx, ny, nz);
    red_add_v4(&g_acc[base + i2], nx, ny, nz);
}

// Kernel 3: normalize and write packed (B,V,3) output.
// Each thread handles 4 vertices: 4x LDG.128 in, 3x STG.128 out.
__global__ void normalize_kernel(float* __restrict__ out) {
    int t = blockIdx.x * blockDim.x + threadIdx.x;
    int gv = t * 4;
    if (gv >= NV) return;

    float4 o[3];
    float* op = reinterpret_cast<float*>(o);

#pragma unroll
    for (int k = 0; k < 4; k++) {
        float4 a = g_acc[gv + k];
        float sq = a.x * a.x + a.y * a.y + a.z * a.z;
        float s = rsqrtf(fmaxf(sq, 1e-12f));
        op[3 * k + 0] = a.x * s;
        op[3 * k + 1] = a.y * s;
        op[3 * k + 2] = a.z * s;
    }

    float4* dst = reinterpret_cast<float4*>(out + (size_t)gv * 3);
    dst[0] = o[0];
    dst[1] = o[1];
    dst[2] = o[2];
}

extern "C" void kernel_launch(void* const* d_in, const int* in_sizes, int n_in,
                              void* d_out, int out_size) {
    const float* verts = (const float*)d_in[0];
    const int*   faces = (const int*)d_in[1];
    float*       out   = (float*)d_out;

    // NV/4 = 1,600,000 threads, 256/block = 6250 blocks (exact).
    repack_zero_kernel<<<NV / 4 / 256, 256>>>(verts);

    dim3 grid((FF + 255) / 256, BB);
    accum_kernel<<<grid, 256>>>(faces);

    normalize_kernel<<<NV / 4 / 256, 256>>>(out);
}

// round 2
// speedup vs baseline: 1.5734x; 1.5734x over previous
#include <cuda_runtime.h>

// Problem constants (fixed by the dataset: B=32, V=200000, F=400000).
#define BB   32
#define VV   200000
#define FF   400000
#define NV   (BB * VV)      // 6,400,000
#define GB   8              // batches per group (lane sub-group)
#define NGRP (BB / GB)      // 4 groups

// Batch-transposed layouts:
//   g_vtxT[(g*VV + v)*GB + j]  = vertex v of batch (g*8+j), as float4 (w=0)
//   g_accT[ same indexing ]    = normal accumulator
// 8 consecutive float4 per vertex = 128B = 4 full 32B sectors.
__device__ float4 g_vtxT[NV];
__device__ float4 g_accT[NV];

__device__ __forceinline__ void red_add_v4(float4* addr, float x, float y, float z) {
    asm volatile("red.global.add.v4.f32 [%0], {%1, %2, %3, %4};"
                 :: "l"(addr), "f"(x), "f"(y), "f"(z), "f"(0.0f)
                 : "memory");
}

// ---------------------------------------------------------------------------
// Kernel 1: transpose-repack vertices into g_vtxT and zero g_accT.
// Block = 256 threads handles 256 vertices x 8 batches of one group.
// SMEM staging keeps both the GMEM reads and writes coalesced.
// smem layout: s[v_local * 25 + b_loc * 3 + c]   (25 = 8*3 + 1 pad)
// ---------------------------------------------------------------------------
#define SP 25
__global__ void repack_zero_kernel(const float* __restrict__ verts) {
    __shared__ float s[256 * SP];
    const int t  = threadIdx.x;
    const int v0 = blockIdx.x * 256;
    const int g  = blockIdx.y;

    // Read phase: 8 batch rows x 256 vertices x 3 floats = 6144 floats, coalesced.
#pragma unroll
    for (int r = 0; r < 24; r++) {
        int idx   = r * 256 + t;           // 0..6143
        int b_loc = idx / 768;             // 0..7
        int off   = idx % 768;             // 0..767
        int vl    = off / 3;
        int c     = off - vl * 3;
        int v     = v0 + vl;
        if (v < VV) {
            size_t src = (size_t)(g * GB + b_loc) * VV * 3 + (size_t)v * 3 + c;
            s[vl * SP + b_loc * 3 + c] = verts[src];
        }
    }
    __syncthreads();

    // Write phase: 256 vertices x 8 slots = 2048 float4, coalesced.
#pragma unroll
    for (int it = 0; it < 8; it++) {
        int w  = it * 256 + t;             // 0..2047
        int vl = w >> 3;
        int j  = w & 7;
        int v  = v0 + vl;
        if (v < VV) {
            const float* p = &s[vl * SP + j * 3];
            size_t dst = (size_t)(g * VV + v) * GB + j;
            g_vtxT[dst] = make_float4(p[0], p[1], p[2], 0.0f);
            g_accT[dst] = make_float4(0.0f, 0.0f, 0.0f, 0.0f);
        }
    }
}

// ---------------------------------------------------------------------------
// Kernel 2: accumulate face normals.
// Thread -> (face f, batch-slot j): j = tid & 7, f = tid >> 3.
// 8 consecutive lanes share a face -> gathers are 128B coalesced (full
// sectors), REDs hit consecutive addresses (full sectors).
// grid.y = group; per-group hot set (~56MB) is L2-resident.
// ---------------------------------------------------------------------------
__global__ void accum_kernel(const int* __restrict__ faces) {
    int t = blockIdx.x * blockDim.x + threadIdx.x;
    int f = t >> 3;
    int j = t & 7;
    if (f >= FF) return;
    size_t base = (size_t)blockIdx.y * VV;

    int i0 = __ldg(&faces[3 * f + 0]);
    int i1 = __ldg(&faces[3 * f + 1]);
    int i2 = __ldg(&faces[3 * f + 2]);

    float4 v0 = g_vtxT[(base + i0) * GB + j];
    float4 v1 = g_vtxT[(base + i1) * GB + j];
    float4 v2 = g_vtxT[(base + i2) * GB + j];

    // e1 = v0 - v1; e2 = v2 - v1; n = cross(e2, e1)
    float e1x = v0.x - v1.x, e1y = v0.y - v1.y, e1z = v0.z - v1.z;
    float e2x = v2.x - v1.x, e2y = v2.y - v1.y, e2z = v2.z - v1.z;

    float nx = e2y * e1z - e2z * e1y;
    float ny = e2z * e1x - e2x * e1z;
    float nz = e2x * e1y - e2y * e1x;

    red_add_v4(&g_accT[(base + i0) * GB + j], nx, ny, nz);
    red_add_v4(&g_accT[(base + i1) * GB + j], nx, ny, nz);
    red_add_v4(&g_accT[(base + i2) * GB + j], nx, ny, nz);
}

// ---------------------------------------------------------------------------
// Kernel 3: normalize and transpose back to (B, V, 3) packed output.
// Mirror of repack: coalesced float4 reads of g_accT, SMEM stage,
// coalesced scalar writes of the output.
// ---------------------------------------------------------------------------
__global__ void normalize_kernel(float* __restrict__ out) {
    __shared__ float s[256 * SP];
    const int t  = threadIdx.x;
    const int v0 = blockIdx.x * 256;
    const int g  = blockIdx.y;

    // Read + normalize: 2048 float4, coalesced.
#pragma unroll
    for (int it = 0; it < 8; it++) {
        int w  = it * 256 + t;
        int vl = w >> 3;
        int j  = w & 7;
        int v  = v0 + vl;
        if (v < VV) {
            float4 a = g_accT[(size_t)(g * VV + v) * GB + j];
            float sq = a.x * a.x + a.y * a.y + a.z * a.z;
            float sc = rsqrtf(fmaxf(sq, 1e-12f));
            float* p = &s[vl * SP + j * 3];
            p[0] = a.x * sc;
            p[1] = a.y * sc;
            p[2] = a.z * sc;
        }
    }
    __syncthreads();

    // Write phase: 6144 floats, coalesced per batch row.
#pragma unroll
    for (int r = 0; r < 24; r++) {
        int idx   = r * 256 + t;
        int b_loc = idx / 768;
        int off   = idx % 768;
        int vl    = off / 3;
        int c     = off - vl * 3;
        int v     = v0 + vl;
        if (v < VV) {
            size_t dst = (size_t)(g * GB + b_loc) * VV * 3 + (size_t)v * 3 + c;
            out[dst] = s[vl * SP + b_loc * 3 + c];
        }
    }
}

extern "C" void kernel_launch(void* const* d_in, const int* in_sizes, int n_in,
                              void* d_out, int out_size) {
    const float* verts = (const float*)d_in[0];
    const int*   faces = (const int*)d_in[1];
    float*       out   = (float*)d_out;

    dim3 vgrid((VV + 255) / 256, NGRP);          // 782 x 4
    repack_zero_kernel<<<vgrid, 256>>>(verts);

    dim3 agrid((FF * GB) / 256, NGRP);           // 12500 x 4
    accum_kernel<<<agrid, 256>>>(faces);

    normalize_kernel<<<vgrid, 256>>>(out);
}

// round 3
// speedup vs baseline: 1.8504x; 1.1760x over previous
#include <cuda_runtime.h>

// Problem constants (fixed by the dataset: B=32, V=200000, F=400000).
#define BB   32
#define VV   200000
#define FF   400000
#define NV   (BB * VV)      // 6,400,000
#define GB   8              // batches per group (lane sub-group)
#define NGRP (BB / GB)      // 4 groups

// Batch-transposed layouts:
//   g_vtxT[(g*VV + v)*GB + j]  = vertex v of batch (g*8+j), float4 (w=0)
//   g_accT[ same indexing ]    = normal accumulator
__device__ float4 g_vtxT[NV];
__device__ float4 g_accT[NV];

__device__ __forceinline__ void red_add_v4(float4* addr, float x, float y, float z) {
    asm volatile("red.global.add.v4.f32 [%0], {%1, %2, %3, %4};"
                 :: "l"(addr), "f"(x), "f"(y), "f"(z), "f"(0.0f)
                 : "memory");
}

// Smem staging: 8 batch rows x 780 floats (768 data + 12 pad).
// Stride 780 -> bank = (12*j + 3*vl + c) % 32 is conflict-free for the
// (vl = w>>3, j = w&7) readback pattern, and 780 % 4 == 0 keeps float4 alignment.
#define SROW 780

// ---------------------------------------------------------------------------
// Kernel 1: transpose-repack vertices into g_vtxT and zero g_accT.
// Fast path: read phase is 6 x LDG.128 per thread (fully coalesced).
// ---------------------------------------------------------------------------
__global__ __launch_bounds__(256) void repack_zero_kernel(const float* __restrict__ verts) {
    __shared__ float s[GB * SROW];
    float4* s4 = reinterpret_cast<float4*>(s);
    const int t  = threadIdx.x;
    const int v0 = blockIdx.x * 256;
    const int g  = blockIdx.y;
    const bool full = (v0 + 256 <= VV);

    if (full) {
        // 8 rows x 192 float4 = 1536 float4, 6 per thread.
#pragma unroll
        for (int rr = 0; rr < 6; rr++) {
            int idx   = rr * 256 + t;          // 0..1535
            int b_loc = idx / 192;
            int k     = idx - b_loc * 192;
            const float4* src = reinterpret_cast<const float4*>(
                verts + (size_t)(g * GB + b_loc) * VV * 3 + (size_t)v0 * 3);
            s4[b_loc * (SROW / 4) + k] = src[k];
        }
    } else {
        // Tail block: scalar guarded path.
        for (int r = 0; r < 24; r++) {
            int idx   = r * 256 + t;
            int b_loc = idx / 768;
            int off   = idx - b_loc * 768;
            int vl    = off / 3;
            if (v0 + vl < VV) {
                size_t src = (size_t)(g * GB + b_loc) * VV * 3 + (size_t)(v0 + vl) * 3
                             + (off - vl * 3);
                s[b_loc * SROW + off] = verts[src];
            }
        }
    }
    __syncthreads();

    // Write phase: 2048 float4 stores, coalesced.
#pragma unroll
    for (int it = 0; it < 8; it++) {
        int w  = it * 256 + t;
        int vl = w >> 3;
        int j  = w & 7;
        int v  = v0 + vl;
        if (v < VV) {
            const float* p = &s[j * SROW + vl * 3];
            size_t dst = ((size_t)g * VV + v) * GB + j;
            g_vtxT[dst] = make_float4(p[0], p[1], p[2], 0.0f);
            g_accT[dst] = make_float4(0.0f, 0.0f, 0.0f, 0.0f);
        }
    }
}

// ---------------------------------------------------------------------------
// Kernel 2: accumulate face normals. 2 faces per thread, 8 batch-slots
// per subgroup of lanes. 6 independent gathers front-batched, then 6 REDs.
// ---------------------------------------------------------------------------
__global__ __launch_bounds__(256) void accum_kernel(const int* __restrict__ faces) {
    int t  = blockIdx.x * blockDim.x + threadIdx.x;
    int j  = t & 7;
    int fp = t >> 3;                 // face pair index, 0..FF/2-1
    int f0 = fp * 2;
    int f1 = f0 + 1;
    size_t base = (size_t)blockIdx.y * VV * GB;

    int a0 = __ldg(&faces[3 * f0 + 0]);
    int a1 = __ldg(&faces[3 * f0 + 1]);
    int a2 = __ldg(&faces[3 * f0 + 2]);
    int b0 = __ldg(&faces[3 * f1 + 0]);
    int b1 = __ldg(&faces[3 * f1 + 1]);
    int b2 = __ldg(&faces[3 * f1 + 2]);

    float4 va0 = g_vtxT[base + (size_t)a0 * GB + j];
    float4 va1 = g_vtxT[base + (size_t)a1 * GB + j];
    float4 va2 = g_vtxT[base + (size_t)a2 * GB + j];
    float4 vb0 = g_vtxT[base + (size_t)b0 * GB + j];
    float4 vb1 = g_vtxT[base + (size_t)b1 * GB + j];
    float4 vb2 = g_vtxT[base + (size_t)b2 * GB + j];

    // Face 0: e1 = v0 - v1; e2 = v2 - v1; n = cross(e2, e1)
    float e1x = va0.x - va1.x, e1y = va0.y - va1.y, e1z = va0.z - va1.z;
    float e2x = va2.x - va1.x, e2y = va2.y - va1.y, e2z = va2.z - va1.z;
    float nax = e2y * e1z - e2z * e1y;
    float nay = e2z * e1x - e2x * e1z;
    float naz = e2x * e1y - e2y * e1x;

    // Face 1
    float f1x = vb0.x - vb1.x, f1y = vb0.y - vb1.y, f1z = vb0.z - vb1.z;
    float f2x = vb2.x - vb1.x, f2y = vb2.y - vb1.y, f2z = vb2.z - vb1.z;
    float nbx = f2y * f1z - f2z * f1y;
    float nby = f2z * f1x - f2x * f1z;
    float nbz = f2x * f1y - f2y * f1x;

    red_add_v4(&g_accT[base + (size_t)a0 * GB + j], nax, nay, naz);
    red_add_v4(&g_accT[base + (size_t)a1 * GB + j], nax, nay, naz);
    red_add_v4(&g_accT[base + (size_t)a2 * GB + j], nax, nay, naz);
    red_add_v4(&g_accT[base + (size_t)b0 * GB + j], nbx, nby, nbz);
    red_add_v4(&g_accT[base + (size_t)b1 * GB + j], nbx, nby, nbz);
    red_add_v4(&g_accT[base + (size_t)b2 * GB + j], nbx, nby, nbz);
}

// ---------------------------------------------------------------------------
// Kernel 3: normalize and transpose back to (B, V, 3) packed output.
// Read phase float4 coalesced; write phase 6 x STG.128 per thread.
// ---------------------------------------------------------------------------
__global__ __launch_bounds__(256) void normalize_kernel(float* __restrict__ out) {
    __shared__ float s[GB * SROW];
    float4* s4 = reinterpret_cast<float4*>(s);
    const int t  = threadIdx.x;
    const int v0 = blockIdx.x * 256;
    const int g  = blockIdx.y;
    const bool full = (v0 + 256 <= VV);

#pragma unroll
    for (int it = 0; it < 8; it++) {
        int w  = it * 256 + t;
        int vl = w >> 3;
        int j  = w & 7;
        int v  = v0 + vl;
        if (v < VV) {
            float4 a = g_accT[((size_t)g * VV + v) * GB + j];
            float sq = a.x * a.x + a.y * a.y + a.z * a.z;
            float sc = rsqrtf(fmaxf(sq, 1e-12f));
            float* p = &s[j * SROW + vl * 3];
            p[0] = a.x * sc;
            p[1] = a.y * sc;
            p[2] = a.z * sc;
        }
    }
    __syncthreads();

    if (full) {
#pragma unroll
        for (int rr = 0; rr < 6; rr++) {
            int idx   = rr * 256 + t;
            int b_loc = idx / 192;
            int k     = idx - b_loc * 192;
            float4* dst = reinterpret_cast<float4*>(
                out + (size_t)(g * GB + b_loc) * VV * 3 + (size_t)v0 * 3);
            dst[k] = s4[b_loc * (SROW / 4) + k];
        }
    } else {
        for (int r = 0; r < 24; r++) {
            int idx   = r * 256 + t;
            int b_loc = idx / 768;
            int off   = idx - b_loc * 768;
            int vl    = off / 3;
            if (v0 + vl < VV) {
                size_t dst = (size_t)(g * GB + b_loc) * VV * 3 + (size_t)(v0 + vl) * 3
                             + (off - vl * 3);
                out[dst] = s[b_loc * SROW + off];
            }
        }
    }
}

extern "C" void kernel_launch(void* const* d_in, const int* in_sizes, int n_in,
                              void* d_out, int out_size) {
    const float* verts = (const float*)d_in[0];
    const int*   faces = (const int*)d_in[1];
    float*       out   = (float*)d_out;

    dim3 vgrid((VV + 255) / 256, NGRP);          // 782 x 4
    repack_zero_kernel<<<vgrid, 256>>>(verts);

    dim3 agrid((FF * GB / 2) / 256, NGRP);       // 6250 x 4
    accum_kernel<<<agrid, 256>>>(faces);

    normalize_kernel<<<vgrid, 256>>>(out);
}